// round 6
// baseline (speedup 1.0000x reference)
#include <cuda_runtime.h>

#define D 128
#define PMAX 512
#define START_SZ 16384

// Scratch (device globals — no allocation allowed)
__device__ float g_vtab[PMAX * D];   // v[p][k] = sum_d W1[d][k] * w2_eff(p)[d]
__device__ float g_ctab[PMAX];       // c[p]    = b1 . w2_eff(p) + b2
__device__ int   g_start[START_SZ];  // first row index of each segment id
__device__ int   g_lastb;            // batch[n-1]

// ---------------------------------------------------------------------------
// Kernel 0: segment boundaries + last segment id  (batch is int32!)
// ---------------------------------------------------------------------------
__global__ void k_bounds(const int* __restrict__ batch, int n) {
    int i = blockIdx.x * blockDim.x + threadIdx.x;
    if (i >= n) return;
    int b = batch[i];
    if (i == 0 || batch[i - 1] != b) {
        if (b >= 0 && b < START_SZ) g_start[b] = i;
    }
    if (i == n - 1) g_lastb = b;
}

// ---------------------------------------------------------------------------
// Kernel 1: per-position fused weight table
//   w2_eff(p)[2j]   =  w2[2j]*cos(p*th_j) + w2[2j+1]*sin(p*th_j)
//   w2_eff(p)[2j+1] =  w2[2j+1]*cos(p*th_j) - w2[2j]*sin(p*th_j)
//   v[p] = W1^T w2_eff(p);  c[p] = b1 . w2_eff(p) + b2
// ---------------------------------------------------------------------------
__global__ void k_table(const float* __restrict__ W1, const float* __restrict__ b1,
                        const float* __restrict__ W2, const float* __restrict__ b2) {
    __shared__ float eff[D];
    int p = blockIdx.x;
    int t = threadIdx.x;
    if (t < D / 2) {
        double theta = pow(10000.0, -2.0 * t / (double)D);
        double ang = (double)p * theta;
        double c = cos(ang), s = sin(ang);
        float w0 = W2[2 * t], w1 = W2[2 * t + 1];
        eff[2 * t]     = (float)(w0 * c + w1 * s);
        eff[2 * t + 1] = (float)(w1 * c - w0 * s);
    }
    __syncthreads();
    float acc = 0.f;
#pragma unroll 8
    for (int d = 0; d < D; d++)
        acc = fmaf(W1[d * D + t], eff[d], acc);
    g_vtab[p * D + t] = acc;
    if (t == 0) {
        float cb = b2[0];
        for (int d = 0; d < D; d++) cb = fmaf(b1[d], eff[d], cb);
        g_ctab[p] = cb;
    }
}

// ---------------------------------------------------------------------------
// Kernel 2: main pass — one warp per row.
//   out[i] = x[i] . v[pos_i] + c[pos_i]
// ---------------------------------------------------------------------------
__global__ void k_main(const float* __restrict__ x,
                       const int* __restrict__ batch,
                       const float* __restrict__ W1,
                       const float* __restrict__ b1,
                       const float* __restrict__ W2,
                       const float* __restrict__ b2,
                       float* __restrict__ out, int n) {
    int i = (int)((blockIdx.x * blockDim.x + threadIdx.x) >> 5);
    int lane = threadIdx.x & 31;
    if (i >= n) return;

    int pos = 0;
    if (lane == 0) {
        int b = batch[i];
        if (b != g_lastb) {
            int st;
            if (b >= 0 && b < START_SZ) {
                st = g_start[b];
            } else {
                // robust fallback: leftmost binary search over sorted batch
                int lo = 0, hi = i;
                while (lo < hi) {
                    int mid = (lo + hi) >> 1;
                    if (batch[mid] < b) lo = mid + 1; else hi = mid;
                }
                st = lo;
            }
            pos = i - st;
        }
    }
    pos = __shfl_sync(0xffffffffu, pos, 0);

    const float4 xv = reinterpret_cast<const float4*>(x)[(size_t)i * (D / 4) + lane];
    float partial;

    if (pos < PMAX) {
        const float4 vv = reinterpret_cast<const float4*>(g_vtab)[pos * (D / 4) + lane];
        partial = xv.x * vv.x + xv.y * vv.y + xv.z * vv.z + xv.w * vv.w;
#pragma unroll
        for (int o = 16; o; o >>= 1) partial += __shfl_xor_sync(0xffffffffu, partial, o);
        if (lane == 0) out[i] = partial + g_ctab[pos];
    } else {
        // Rare fallback (pos beyond table): compute w2_eff + v on the fly.
        float4 w2v = reinterpret_cast<const float4*>(W2)[lane];
        float eff0, eff1, eff2, eff3;
        {
            int j0 = 2 * lane;          // pair for dims 4*lane, 4*lane+1
            double th0 = pow(10000.0, -2.0 * j0 / (double)D);
            double a0 = (double)pos * th0;
            double c0 = cos(a0), s0 = sin(a0);
            eff0 = (float)(w2v.x * c0 + w2v.y * s0);
            eff1 = (float)(w2v.y * c0 - w2v.x * s0);
            int j1 = 2 * lane + 1;      // pair for dims 4*lane+2, 4*lane+3
            double th1 = pow(10000.0, -2.0 * j1 / (double)D);
            double a1 = (double)pos * th1;
            double c1 = cos(a1), s1 = sin(a1);
            eff2 = (float)(w2v.z * c1 + w2v.w * s1);
            eff3 = (float)(w2v.w * c1 - w2v.z * s1);
        }
        float4 acc = make_float4(0.f, 0.f, 0.f, 0.f);
        for (int src = 0; src < 32; src++) {
            float e0 = __shfl_sync(0xffffffffu, eff0, src);
            float e1 = __shfl_sync(0xffffffffu, eff1, src);
            float e2 = __shfl_sync(0xffffffffu, eff2, src);
            float e3 = __shfl_sync(0xffffffffu, eff3, src);
            const float4* W1r = reinterpret_cast<const float4*>(W1);
            float4 a = W1r[(4 * src + 0) * (D / 4) + lane];
            acc.x = fmaf(a.x, e0, acc.x); acc.y = fmaf(a.y, e0, acc.y);
            acc.z = fmaf(a.z, e0, acc.z); acc.w = fmaf(a.w, e0, acc.w);
            float4 bq = W1r[(4 * src + 1) * (D / 4) + lane];
            acc.x = fmaf(bq.x, e1, acc.x); acc.y = fmaf(bq.y, e1, acc.y);
            acc.z = fmaf(bq.z, e1, acc.z); acc.w = fmaf(bq.w, e1, acc.w);
            float4 cq = W1r[(4 * src + 2) * (D / 4) + lane];
            acc.x = fmaf(cq.x, e2, acc.x); acc.y = fmaf(cq.y, e2, acc.y);
            acc.z = fmaf(cq.z, e2, acc.z); acc.w = fmaf(cq.w, e2, acc.w);
            float4 dq = W1r[(4 * src + 3) * (D / 4) + lane];
            acc.x = fmaf(dq.x, e3, acc.x); acc.y = fmaf(dq.y, e3, acc.y);
            acc.z = fmaf(dq.z, e3, acc.z); acc.w = fmaf(dq.w, e3, acc.w);
        }
        float4 b1v = reinterpret_cast<const float4*>(b1)[lane];
        partial = xv.x * acc.x + xv.y * acc.y + xv.z * acc.z + xv.w * acc.w
                + b1v.x * eff0 + b1v.y * eff1 + b1v.z * eff2 + b1v.w * eff3;
#pragma unroll
        for (int o = 16; o; o >>= 1) partial += __shfl_xor_sync(0xffffffffu, partial, o);
        if (lane == 0) out[i] = partial + b2[0];
    }
}

// ---------------------------------------------------------------------------
extern "C" void kernel_launch(void* const* d_in, const int* in_sizes, int n_in,
                              void* d_out, int out_size) {
    const float* x     = (const float*)d_in[0];
    const int*   batch = (const int*)d_in[1];       // int32 (JAX x64 disabled)
    const float* W1    = (const float*)d_in[2];
    const float* b1    = (const float*)d_in[3];
    const float* W2    = (const float*)d_in[4];
    const float* b2    = (const float*)d_in[5];
    float*       out   = (float*)d_out;
    int n = in_sizes[1];  // N rows (batch has N elements)

    k_bounds<<<(n + 255) / 256, 256>>>(batch, n);
    k_table<<<PMAX, D>>>(W1, b1, W2, b2);
    k_main<<<(n + 7) / 8, 256>>>(x, batch, W1, b1, W2, b2, out, n);
}